// round 4
// baseline (speedup 1.0000x reference)
#include <cuda_runtime.h>
#include <cstdint>
#include <cstddef>

#define B_ 256
#define T_ 256
#define D_ 512
#define H_ 1024
#define C_ 10

#define NCTA 128
#define NTHR 256
#define TM 32
#define TN 64
#define TK 32

// h ping-pong buffers: h after step t lives in g_h[(t+1)&1].
// t=0 never reads h (h0 == 0 handled by skipping U-GEMM and beta term),
// so no initialization is required and graph replay is deterministic.
// Referenced ONLY from device code (host address-of a __device__ symbol
// resolves to the host shadow and trips the memory guard).
__device__ float g_h[2][B_ * H_];

// One fused recurrence step:
//   h_out = alpha * tanh(x_t @ Ww + h_in @ Uw + (Wb+Ub)) + beta * h_in
// Grid: 128 CTAs = 8 M-tiles(32) x 16 N-tiles(64). 256 threads, 2x4 per thread.
// Double-buffered smem pipeline, one __syncthreads per k-tile.
__global__ void __launch_bounds__(NTHR, 1) step_kernel(
    const float* __restrict__ x,
    const float* __restrict__ Ww, const float* __restrict__ Wb,
    const float* __restrict__ Uw, const float* __restrict__ Ub,
    const float* __restrict__ alpha_p, const float* __restrict__ beta_p,
    int t)
{
    const float* __restrict__ h_in  = &g_h[t & 1][0];
    float* __restrict__       h_out = &g_h[(t + 1) & 1][0];

    __shared__ float As[2][TK][TM + 2];  // A transposed: As[p][k][m]
    __shared__ float Bs[2][TK][TN];

    const int tid = threadIdx.x;
    const int bm = blockIdx.x & 7;    // 8 M-tiles of 32
    const int bn = blockIdx.x >> 3;   // 16 N-tiles of 64
    const int m0 = bm * TM;
    const int n0 = bn * TN;

    const int tx = tid & 15;          // 16 col-groups
    const int ty = tid >> 4;          // 16 row-groups
    const int mr = ty * 2;            // 2 rows per thread
    const int nc = tx * 4;            // 4 cols per thread

    const float alpha = alpha_p[0];
    const float beta  = beta_p[0];

    float bias[4];
    #pragma unroll
    for (int j = 0; j < 4; ++j)
        bias[j] = Wb[n0 + nc + j] + Ub[n0 + nc + j];

    // Tile-loader lane mapping
    const int a_row = tid >> 3;          // 0..31
    const int a_k4  = (tid & 7) << 2;    // 0,4,...,28
    const int b_k   = tid >> 4;          // 0..15 (and +16)
    const int b_n4  = (tid & 15) << 2;   // 0..60

    float acc[2][4];
    #pragma unroll
    for (int i = 0; i < 2; ++i)
        #pragma unroll
        for (int j = 0; j < 4; ++j) acc[i][j] = 0.f;

    // Global bases for the two GEMM parts
    const float* A1 = x + ((size_t)(m0 + a_row) * T_ + (size_t)t) * D_ + a_k4;  // x row, step t
    const float* B1 = Ww + (size_t)b_k * H_ + n0 + b_n4;                        // Ww[k][n]
    const float* A2 = h_in + (size_t)(m0 + a_row) * H_ + a_k4;                  // h row
    const float* B2 = Uw + (size_t)b_k * H_ + n0 + b_n4;                        // Uw[k][n]

    // ---- helpers (macros keep everything in registers) ----
#define LOAD_TILE(Aptr, Bptr, k0, av, bv0, bv1)                    \
    do {                                                            \
        av  = *(const float4*)((Aptr) + (k0));                      \
        const float* _bp = (Bptr) + (size_t)(k0) * H_;              \
        bv0 = *(const float4*)_bp;                                  \
        bv1 = *(const float4*)(_bp + 16 * H_);                      \
    } while (0)

#define STORE_TILE(p, av, bv0, bv1)                                 \
    do {                                                            \
        As[p][a_k4 + 0][a_row] = av.x;                              \
        As[p][a_k4 + 1][a_row] = av.y;                              \
        As[p][a_k4 + 2][a_row] = av.z;                              \
        As[p][a_k4 + 3][a_row] = av.w;                              \
        *(float4*)&Bs[p][b_k][b_n4]      = bv0;                     \
        *(float4*)&Bs[p][b_k + 16][b_n4] = bv1;                     \
    } while (0)

#define COMPUTE_TILE(p)                                             \
    do {                                                            \
        _Pragma("unroll")                                           \
        for (int kk = 0; kk < TK; ++kk) {                           \
            float2 a = *(const float2*)&As[p][kk][mr];              \
            float4 b = *(const float4*)&Bs[p][kk][nc];              \
            acc[0][0] += a.x * b.x; acc[0][1] += a.x * b.y;         \
            acc[0][2] += a.x * b.z; acc[0][3] += a.x * b.w;         \
            acc[1][0] += a.y * b.x; acc[1][1] += a.y * b.y;         \
            acc[1][2] += a.y * b.z; acc[1][3] += a.y * b.w;         \
        }                                                           \
    } while (0)

    float4 av, bv0, bv1;
    int p = 0;

    // Preload first tile of part 1
    LOAD_TILE(A1, B1, 0, av, bv0, bv1);
    STORE_TILE(0, av, bv0, bv1);
    __syncthreads();

    // ======== part 1: x_t @ Ww  (K = D_) ========
    #pragma unroll 1
    for (int k0 = TK; k0 < D_; k0 += TK) {
        LOAD_TILE(A1, B1, k0, av, bv0, bv1);
        COMPUTE_TILE(p);
        STORE_TILE(p ^ 1, av, bv0, bv1);
        __syncthreads();
        p ^= 1;
    }

    if (t > 0) {
        // bridge: prefetch first tile of part 2 while computing last of part 1
        LOAD_TILE(A2, B2, 0, av, bv0, bv1);
        COMPUTE_TILE(p);
        STORE_TILE(p ^ 1, av, bv0, bv1);
        __syncthreads();
        p ^= 1;

        // ======== part 2: h @ Uw  (K = H_) ========
        #pragma unroll 1
        for (int k0 = TK; k0 < H_; k0 += TK) {
            LOAD_TILE(A2, B2, k0, av, bv0, bv1);
            COMPUTE_TILE(p);
            STORE_TILE(p ^ 1, av, bv0, bv1);
            __syncthreads();
            p ^= 1;
        }
        COMPUTE_TILE(p);
    } else {
        COMPUTE_TILE(p);
    }

    // ======== epilogue: h_out = alpha*tanh(acc+bias) + beta*h_in ========
    #pragma unroll
    for (int i = 0; i < 2; ++i) {
        const int gm = m0 + mr + i;
        const size_t o = (size_t)gm * H_ + (size_t)(n0 + nc);
        float4 hp = make_float4(0.f, 0.f, 0.f, 0.f);
        if (t > 0) hp = *(const float4*)(h_in + o);
        float4 r;
        r.x = alpha * tanhf(acc[i][0] + bias[0]) + beta * hp.x;
        r.y = alpha * tanhf(acc[i][1] + bias[1]) + beta * hp.y;
        r.z = alpha * tanhf(acc[i][2] + bias[2]) + beta * hp.z;
        r.w = alpha * tanhf(acc[i][3] + bias[3]) + beta * hp.w;
        *(float4*)(h_out + o) = r;
    }

#undef LOAD_TILE
#undef STORE_TILE
#undef COMPUTE_TILE
}

// out[row, c] = h_final[row, :] @ fc_w[:, c] + fc_b[c]
// One CTA per batch row; warp w computes column w (C_=10 warps).
// Final h is in g_h[0] (T_ even), referenced on-device.
__global__ void fc_kernel(const float* __restrict__ fcw,
                          const float* __restrict__ fcb,
                          float* __restrict__ out)
{
    const float* __restrict__ h = &g_h[0][0];
    const int row  = blockIdx.x;
    const int warp = threadIdx.x >> 5;
    const int lane = threadIdx.x & 31;
    if (warp >= C_) return;
    float s = 0.f;
    const float* hr = h + (size_t)row * H_;
    for (int k = lane; k < H_; k += 32)
        s += hr[k] * fcw[k * C_ + warp];
    #pragma unroll
    for (int off = 16; off > 0; off >>= 1)
        s += __shfl_down_sync(0xffffffffu, s, off);
    if (lane == 0) out[row * C_ + warp] = s + fcb[warp];
}

extern "C" void kernel_launch(void* const* d_in, const int* in_sizes, int n_in,
                              void* d_out, int out_size)
{
    (void)in_sizes; (void)n_in; (void)out_size;
    const float* x   = (const float*)d_in[0];
    const float* Ww  = (const float*)d_in[1];
    const float* Wb  = (const float*)d_in[2];
    const float* Uw  = (const float*)d_in[3];
    const float* Ub  = (const float*)d_in[4];
    const float* al  = (const float*)d_in[5];
    const float* be  = (const float*)d_in[6];
    const float* fcw = (const float*)d_in[7];
    const float* fcb = (const float*)d_in[8];

    for (int t = 0; t < T_; ++t)
        step_kernel<<<NCTA, NTHR>>>(x, Ww, Wb, Uw, Ub, al, be, t);

    fc_kernel<<<B_, 32 * C_>>>(fcw, fcb, (float*)d_out);
}